// round 2
// baseline (speedup 1.0000x reference)
#include <cuda_runtime.h>
#include <math.h>

#define USERN 50000
#define NNODE 100000
#define DLAT  64
#define HNUM  128
#define NE    1600000
#define N64   (NNODE*DLAT)

// scratch (static device globals: allocation-free per harness rules)
__device__ float g_cur[N64];
__device__ float g_aij[N64];
__device__ float g_gx[N64];
__device__ float g_tem[N64];
__device__ float g_allH[NNODE*HNUM];
__device__ float g_lat[HNUM*DLAT];
__device__ int   g_cnt[NNODE];
__device__ int   g_fill[NNODE];
__device__ int   g_rowptr[NNODE+1];
__device__ int   g_ecol[NE];
__device__ float g_eval[NE];

__device__ __forceinline__ float lrelu(float x){ return x > 0.f ? x : 0.5f*x; }

// concat(u,i) -> cur ; aij = 2*sigmoid(z)-1 = tanh(z/2) ; zero CSR counters
__global__ void __launch_bounds__(256) k_prep(const float* __restrict__ u,
                                              const float* __restrict__ it,
                                              const float* __restrict__ z){
  int i = blockIdx.x*256 + threadIdx.x;          // grid covers N64/4 exactly
  if (i < NNODE){ g_cnt[i] = 0; g_fill[i] = 0; }
  float4 e;
  if (i < (USERN*DLAT)/4) e = ((const float4*)u)[i];
  else                    e = ((const float4*)it)[i - (USERN*DLAT)/4];
  ((float4*)g_cur)[i] = e;
  float4 zz = ((const float4*)z)[i];
  float4 a;
  a.x = tanhf(0.5f*zz.x); a.y = tanhf(0.5f*zz.y);
  a.z = tanhf(0.5f*zz.z); a.w = tanhf(0.5f*zz.w);
  ((float4*)g_aij)[i] = a;
}

__global__ void __launch_bounds__(256) k_hist(const int* __restrict__ rows){
  int e = blockIdx.x*256 + threadIdx.x;          // grid == NE exactly
  atomicAdd(&g_cnt[rows[e]], 1);
}

// single-block exclusive scan of g_cnt -> g_rowptr (register-light, 256 thr)
__global__ void __launch_bounds__(256) k_scan(){
  __shared__ int ssum[256];
  int t = threadIdx.x;
  const int CH = 391;                             // 256*391 >= NNODE
  int base = t*CH;
  int s = 0;
  for (int i=0;i<CH;i++){ int idx=base+i; if (idx<NNODE) s += g_cnt[idx]; }
  ssum[t] = s; __syncthreads();
  // serial-friendly Hillis-Steele inclusive scan over 256 partials
  for (int off=1; off<256; off<<=1){
    int v = (t>=off) ? ssum[t-off] : 0;
    __syncthreads();
    ssum[t] += v;
    __syncthreads();
  }
  int run = (t==0) ? 0 : ssum[t-1];
  for (int i=0;i<CH;i++){ int idx=base+i; if (idx<NNODE){ g_rowptr[idx]=run; run += g_cnt[idx]; } }
  if (t==255) g_rowptr[NNODE] = NE;
}

__global__ void __launch_bounds__(256) k_scatter(const int* __restrict__ rows,
                                                 const int* __restrict__ cols,
                                                 const float* __restrict__ vals){
  int e = blockIdx.x*256 + threadIdx.x;          // grid == NE exactly
  int r = rows[e];
  int p = g_rowptr[r] + atomicAdd(&g_fill[r], 1);
  g_ecol[p] = cols[e];
  g_eval[p] = vals[e];
}

// allH[N,128] = cur[N,64] @ Hyper[64,128].  Hyper staged in smem (32KB).
__global__ void __launch_bounds__(256) k_allH(const float* __restrict__ Hyp){
  __shared__ float sH[DLAT][HNUM];
  int t = threadIdx.x;
  for (int i=t; i<DLAT*HNUM; i+=256) sH[i>>7][i&127] = Hyp[i];
  __syncthreads();
  int row = blockIdx.x*32 + (t>>3);              // 3125 blocks * 32 rows == NNODE
  int cs  = (t&7)*4;
  const float* arow = g_cur + row*DLAT;
  float4 acc[4];
  #pragma unroll
  for (int j=0;j<4;j++) acc[j] = make_float4(0.f,0.f,0.f,0.f);
  for (int k=0;k<DLAT;k++){
    float a = arow[k];                            // L1-resident (row shared by 8 thr)
    #pragma unroll
    for (int j=0;j<4;j++){
      float4 h = *(const float4*)&sH[k][cs + 32*j];
      acc[j].x += a*h.x; acc[j].y += a*h.y; acc[j].z += a*h.z; acc[j].w += a*h.w;
    }
  }
  float* o = g_allH + row*HNUM;
  #pragma unroll
  for (int j=0;j<4;j++) *(float4*)&o[cs + 32*j] = acc[j];
}

// gx = cur * aij ; also zero g_lat for this layer's reduction
__global__ void __launch_bounds__(256) k_gx(){
  int i = blockIdx.x*256 + threadIdx.x;          // grid covers N64/4 exactly
  float4 c = ((const float4*)g_cur)[i];
  float4 a = ((const float4*)g_aij)[i];
  float4 g; g.x=c.x*a.x; g.y=c.y*a.y; g.z=c.z*a.z; g.w=c.w*a.w;
  ((float4*)g_gx)[i] = g;
  if (i < (HNUM*DLAT)/4) ((float4*)g_lat)[i] = make_float4(0.f,0.f,0.f,0.f);
}

// tem[r,:] = leaky( sum_e val[e] * gx[col[e],:] )  -- one warp per row, CSR gather
__global__ void __launch_bounds__(256) k_spmm(){
  int w    = (blockIdx.x*256 + threadIdx.x) >> 5; // 12500 blocks * 8 warps == NNODE
  int lane = threadIdx.x & 31;
  int beg = g_rowptr[w], end = g_rowptr[w+1];
  float ax = 0.f, ay = 0.f;
  for (int j=beg; j<end; j++){
    int   c = g_ecol[j];                          // uniform within warp
    float v = g_eval[j];
    float2 x = *(const float2*)&g_gx[c*DLAT + lane*2];  // coalesced 256B/warp, L2-hit
    ax += v*x.x; ay += v*x.y;
  }
  float2 o; o.x = lrelu(ax); o.y = lrelu(ay);
  *(float2*)&g_tem[w*DLAT + lane*2] = o;
}

// lat[128,64] += allH^T @ cur  (reduction over N, block partials -> atomicAdd)
__global__ void __launch_bounds__(256) k_lat(){
  __shared__ float sHyp[32][HNUM];
  __shared__ float sCur[32][DLAT];
  int t  = threadIdx.x;
  int td = t & 15, th = t >> 4;                   // thread: h in [th*8,th*8+8), d in [td*4,td*4+4)
  float acc[8][4];
  #pragma unroll
  for (int i=0;i<8;i++)
    #pragma unroll
    for (int j=0;j<4;j++) acc[i][j] = 0.f;
  for (int base = blockIdx.x*32; base < NNODE; base += gridDim.x*32){
    for (int i=t; i<32*HNUM; i+=256){
      int r=i>>7, c=i&127;
      sHyp[r][c] = g_allH[(base+r)*HNUM + c];
    }
    for (int i=t; i<32*DLAT; i+=256){
      int r=i>>6, c=i&63;
      sCur[r][c] = g_cur[(base+r)*DLAT + c];
    }
    __syncthreads();
    for (int r=0;r<32;r++){
      float4 h0 = *(const float4*)&sHyp[r][th*8];
      float4 h1 = *(const float4*)&sHyp[r][th*8+4];
      float4 cv = *(const float4*)&sCur[r][td*4];
      float hv[8] = {h0.x,h0.y,h0.z,h0.w,h1.x,h1.y,h1.z,h1.w};
      float cc[4] = {cv.x,cv.y,cv.z,cv.w};
      #pragma unroll
      for (int i=0;i<8;i++)
        #pragma unroll
        for (int j=0;j<4;j++)
          acc[i][j] += hv[i]*cc[j];
    }
    __syncthreads();
  }
  #pragma unroll
  for (int i=0;i<8;i++)
    #pragma unroll
    for (int j=0;j<4;j++)
      atomicAdd(&g_lat[(th*8+i)*DLAT + td*4 + j], acc[i][j]);
}

// hl = leaky( allH @ leaky(lat) ); out[1+L]=hl; cur=hl+tem; (L==1: out[0]=tem)
__global__ void __launch_bounds__(256) k_hl(float* __restrict__ out, int layer){
  __shared__ float sLat[HNUM][DLAT];
  int t = threadIdx.x;
  for (int i=t; i<HNUM*DLAT; i+=256) sLat[i>>6][i&63] = lrelu(g_lat[i]);
  __syncthreads();
  int row = blockIdx.x*64 + (t>>2);
  int cs  = (t&3)*4;                              // cols cs+16j+{0..3}
  if (row < NNODE){
    const float* arow = g_allH + row*HNUM;
    float4 acc[4];
    #pragma unroll
    for (int j=0;j<4;j++) acc[j] = make_float4(0.f,0.f,0.f,0.f);
    for (int k=0;k<HNUM;k++){
      float a = arow[k];                          // L1-resident (row shared by 4 thr)
      #pragma unroll
      for (int j=0;j<4;j++){
        float4 h = *(const float4*)&sLat[k][cs + 16*j];
        acc[j].x += a*h.x; acc[j].y += a*h.y; acc[j].z += a*h.z; acc[j].w += a*h.w;
      }
    }
    float* o1 = out + (size_t)(1+layer)*N64 + row*DLAT;
    float* o0 = out + row*DLAT;
    #pragma unroll
    for (int j=0;j<4;j++){
      int col = cs + 16*j;
      float4 h;
      h.x = lrelu(acc[j].x); h.y = lrelu(acc[j].y);
      h.z = lrelu(acc[j].z); h.w = lrelu(acc[j].w);
      *(float4*)&o1[col] = h;
      float4 tv = *(const float4*)&g_tem[row*DLAT + col];
      float4 cv; cv.x=h.x+tv.x; cv.y=h.y+tv.y; cv.z=h.z+tv.z; cv.w=h.w+tv.w;
      *(float4*)&g_cur[row*DLAT + col] = cv;
      if (layer == 1) *(float4*)&o0[col] = tv;    // final tem -> out slot 0
    }
  }
}

extern "C" void kernel_launch(void* const* d_in, const int* in_sizes, int n_in,
                              void* d_out, int out_size){
  const int*   rows = (const int*)  d_in[0];
  const int*   cols = (const int*)  d_in[1];
  const float* vals = (const float*)d_in[2];
  const float* u    = (const float*)d_in[3];
  const float* it   = (const float*)d_in[4];
  const float* Hy   = (const float*)d_in[5];
  const float* z    = (const float*)d_in[6];
  // d_in[7] = keepRate == 1 (static: no dropout path)
  float* out = (float*)d_out;

  k_prep<<<6250,256>>>(u, it, z);
  k_hist<<<6250,256>>>(rows);
  k_scan<<<1,256>>>();
  k_scatter<<<6250,256>>>(rows, cols, vals);
  k_allH<<<3125,256>>>(Hy);
  for (int L=0; L<2; L++){
    k_gx<<<6250,256>>>();
    k_spmm<<<12500,256>>>();
    k_lat<<<296,256>>>();
    k_hl<<<1563,256>>>(out, L);
  }
  (void)in_sizes; (void)n_in; (void)out_size;
}

// round 3
// speedup vs baseline: 1.6326x; 1.6326x over previous
#include <cuda_runtime.h>
#include <math.h>

#define USERN 50000
#define NNODE 100000
#define DLAT  64
#define HNUM  128
#define NE    1600000
#define N64   (NNODE*DLAT)
#define NBLK  391          // ceil(NNODE/256)

// scratch (static device globals: allocation-free per harness rules)
__device__ float g_cur[N64];
__device__ float g_aij[N64];
__device__ float g_gx[N64];
__device__ float g_tem[N64];
__device__ float g_allH[NNODE*HNUM];
__device__ float g_lat[HNUM*DLAT];
__device__ int   g_cnt[NNODE];
__device__ int   g_fill[NNODE];
__device__ int   g_rowptr[NNODE+1];
__device__ int   g_bsum[NBLK];
__device__ int   g_boff[NBLK];
__device__ unsigned long long g_epack[NE];

typedef unsigned long long ull;

__device__ __forceinline__ float lrelu(float x){ return x > 0.f ? x : 0.5f*x; }

// tanh(x/2) = 2*sigmoid(x)-1, via exp(-|x|)
__device__ __forceinline__ float tanh_half(float x){
  float t = __expf(-fabsf(x));
  float r = __fdividef(1.f - t, 1.f + t);
  return copysignf(r, x);
}

// ---- packed f32x2 FMA helpers (Blackwell) ----
__device__ __forceinline__ ull ffma2(ull d, ull a, ull b){
  asm("fma.rn.f32x2 %0, %1, %2, %0;" : "+l"(d) : "l"(a), "l"(b));
  return d;
}
__device__ __forceinline__ ull pack2(float x, float y){
  ull r; asm("mov.b64 %0, {%1, %2};" : "=l"(r) : "f"(x), "f"(y)); return r;
}
__device__ __forceinline__ float2 unpack2(ull v){
  float2 r; asm("mov.b64 {%0, %1}, %2;" : "=f"(r.x), "=f"(r.y) : "l"(v)); return r;
}

// ===========================================================================
// k_allH: allH[N,128] = cur[N,64] @ Hyper[64,128], fused with prep:
//   cur = concat(u,i); aij = tanh(z/2); gx = cur*aij; g_cnt = 0
// Block: 128 thr, tile M=64 N=128 K=64. Thread: 8x8. f32x2 FMA.
// sA [m][k] with XOR-swizzled k-quad: phys_kq = kq ^ (m>>3)  (conflict-free)
// ===========================================================================
__global__ void __launch_bounds__(128, 4) k_allH(const float* __restrict__ u,
                                                 const float* __restrict__ it,
                                                 const float* __restrict__ z,
                                                 const float* __restrict__ Hyp){
  __shared__ float sA[64*64];    // 16KB [m][k] swizzled
  __shared__ float sB[64*HNUM];  // 32KB [k][n]
  int t = threadIdx.x;
  int R = blockIdx.x*64;

  for (int i=t; i<64*HNUM/4; i+=128) ((float4*)sB)[i] = ((const float4*)Hyp)[i];

  #pragma unroll
  for (int i=0;i<8;i++){
    int slot = i*128 + t;              // 1024 slots = 64 rows x 16 quads
    int m = slot>>4, kc = slot&15;
    int r = R + m;
    float4 v = make_float4(0.f,0.f,0.f,0.f);
    if (r < NNODE){
      const float4* src = (r < USERN) ? ((const float4*)u) + (size_t)r*16
                                      : ((const float4*)it) + (size_t)(r-USERN)*16;
      v = src[kc];
    }
    *(float4*)&sA[m*64 + ((kc ^ (m>>3))<<2)] = v;
    if (r < NNODE){
      ((float4*)g_cur)[(size_t)r*16 + kc] = v;
      float4 zz = ((const float4*)z)[(size_t)r*16 + kc];
      float4 a4; a4.x=tanh_half(zz.x); a4.y=tanh_half(zz.y);
                 a4.z=tanh_half(zz.z); a4.w=tanh_half(zz.w);
      ((float4*)g_aij)[(size_t)r*16 + kc] = a4;
      float4 g; g.x=v.x*a4.x; g.y=v.y*a4.y; g.z=v.z*a4.z; g.w=v.w*a4.w;
      ((float4*)g_gx)[(size_t)r*16 + kc] = g;
    }
  }
  if (t < 64){ int r = R + t; if (r < NNODE) g_cnt[r] = 0; }
  __syncthreads();

  int tm = t>>4, tn = t&15;            // 8 m-groups x 16 n-groups
  int m0 = tm*8, n0 = tn*8;
  ull acc[8][4];
  #pragma unroll
  for (int j=0;j<8;j++){ acc[j][0]=0; acc[j][1]=0; acc[j][2]=0; acc[j][3]=0; }

  #pragma unroll
  for (int kq=0;kq<16;kq++){
    float4 aq[8];
    int sw = (kq ^ tm) << 2;           // (m0+j)>>3 == tm for j<8
    #pragma unroll
    for (int j=0;j<8;j++) aq[j] = *(const float4*)&sA[(m0+j)*64 + sw];
    #pragma unroll
    for (int c=0;c<4;c++){
      int k = kq*4+c;
      float4 b0 = *(const float4*)&sB[k*HNUM + n0];
      float4 b1 = *(const float4*)&sB[k*HNUM + n0 + 4];
      ull bp0=pack2(b0.x,b0.y), bp1=pack2(b0.z,b0.w);
      ull bp2=pack2(b1.x,b1.y), bp3=pack2(b1.z,b1.w);
      #pragma unroll
      for (int j=0;j<8;j++){
        float av = (c==0)?aq[j].x:(c==1)?aq[j].y:(c==2)?aq[j].z:aq[j].w;
        ull ad = pack2(av,av);
        acc[j][0]=ffma2(acc[j][0],ad,bp0);
        acc[j][1]=ffma2(acc[j][1],ad,bp1);
        acc[j][2]=ffma2(acc[j][2],ad,bp2);
        acc[j][3]=ffma2(acc[j][3],ad,bp3);
      }
    }
  }
  #pragma unroll
  for (int j=0;j<8;j++){
    int r = R + m0 + j;
    if (r < NNODE){
      float2 v0=unpack2(acc[j][0]), v1=unpack2(acc[j][1]);
      float2 v2=unpack2(acc[j][2]), v3=unpack2(acc[j][3]);
      *(float4*)&g_allH[(size_t)r*HNUM + n0]     = make_float4(v0.x,v0.y,v1.x,v1.y);
      *(float4*)&g_allH[(size_t)r*HNUM + n0 + 4] = make_float4(v2.x,v2.y,v3.x,v3.y);
    }
  }
}

// ===========================================================================
// CSR build: hist -> 3-stage scan -> scatter (packed 8B edge records)
// ===========================================================================
__global__ void __launch_bounds__(256) k_hist(const int* __restrict__ rows){
  int e = blockIdx.x*256 + threadIdx.x;            // grid == NE exactly
  atomicAdd(&g_cnt[rows[e]], 1);
}

__global__ void __launch_bounds__(256) k_scanA(){
  int idx = blockIdx.x*256 + threadIdx.x;
  int c = (idx < NNODE) ? g_cnt[idx] : 0;
  int lane = threadIdx.x&31, wid = threadIdx.x>>5;
  #pragma unroll
  for (int off=16;off;off>>=1) c += __shfl_down_sync(0xffffffffu, c, off);
  __shared__ int ws[8];
  if (lane==0) ws[wid]=c;
  __syncthreads();
  if (threadIdx.x==0){ int s=0; for(int i=0;i<8;i++) s+=ws[i]; g_bsum[blockIdx.x]=s; }
}

__global__ void __launch_bounds__(512) k_scanB(){
  __shared__ int s[512];
  int t = threadIdx.x;
  int v0 = (t < NBLK) ? g_bsum[t] : 0;
  s[t] = v0; __syncthreads();
  for (int off=1;off<512;off<<=1){
    int v = (t>=off) ? s[t-off] : 0;
    __syncthreads(); s[t]+=v; __syncthreads();
  }
  if (t < NBLK) g_boff[t] = s[t] - v0;             // exclusive
  if (t==0) g_rowptr[NNODE] = NE;
}

__global__ void __launch_bounds__(256) k_scanC(){
  int b = blockIdx.x, t = threadIdx.x;
  int idx = b*256 + t;
  int c = (idx < NNODE) ? g_cnt[idx] : 0;
  int lane = t&31, wid = t>>5;
  int incl = c;
  #pragma unroll
  for (int off=1;off<32;off<<=1){
    int y = __shfl_up_sync(0xffffffffu, incl, off);
    if (lane>=off) incl += y;
  }
  __shared__ int ws[8];
  if (lane==31) ws[wid]=incl;
  __syncthreads();
  if (t < 8){
    int v = ws[t], s = v;
    #pragma unroll
    for (int off=1;off<8;off<<=1){
      int y = __shfl_up_sync(0xffu, s, off);
      if (t>=off) s += y;
    }
    ws[t] = s - v;
  }
  __syncthreads();
  int excl = incl - c + ws[wid] + g_boff[b];
  if (idx < NNODE){ g_rowptr[idx] = excl; g_fill[idx] = excl; }
}

__global__ void __launch_bounds__(256) k_scatter(const int* __restrict__ rows,
                                                 const int* __restrict__ cols,
                                                 const float* __restrict__ vals){
  int e = blockIdx.x*256 + threadIdx.x;            // grid == NE exactly
  int r = rows[e];
  int p = atomicAdd(&g_fill[r], 1);
  g_epack[p] = ((ull)__float_as_uint(vals[e])<<32) | (unsigned)cols[e];
}

// ===========================================================================
// k_spmm: tem[r,:] = leaky( sum_e val*gx[col,:] ), warp per row.
// block 0 also zeroes g_lat for the upcoming k_lat.
// ===========================================================================
__global__ void __launch_bounds__(256) k_spmm(){
  if (blockIdx.x == 0){
    for (int i=threadIdx.x; i<HNUM*DLAT; i+=256) g_lat[i] = 0.f;
  }
  int w    = (blockIdx.x*256 + threadIdx.x) >> 5; // 12500 blocks * 8 warps == NNODE
  int lane = threadIdx.x & 31;
  int beg = g_rowptr[w], end = g_rowptr[w+1];
  float ax = 0.f, ay = 0.f;
  for (int j=beg; j<end; j++){
    ull p = g_epack[j];                            // lane-uniform broadcast
    int   c = (int)(unsigned)(p & 0xffffffffu);
    float v = __uint_as_float((unsigned)(p>>32));
    float2 x = *(const float2*)&g_gx[(size_t)c*DLAT + lane*2];
    ax = fmaf(v, x.x, ax); ay = fmaf(v, x.y, ay);
  }
  float2 o; o.x = lrelu(ax); o.y = lrelu(ay);
  *(float2*)&g_tem[(size_t)w*DLAT + lane*2] = o;
}

// ===========================================================================
// k_lat: lat[128,64] += allH^T @ cur  (reduce over N rows; REDG at end)
// 256 thr, thread = 4H x 8D; 32-row smem tiles; f32x2 FMA.
// ===========================================================================
__global__ void __launch_bounds__(256) k_lat(){
  __shared__ float sH[32*HNUM];   // 16KB
  __shared__ float sC[32*DLAT];   // 8KB
  int t = threadIdx.x;
  int th = t>>3, td = t&7;        // 32 h-groups x 8 d-groups
  int h0 = th*4, d0 = td*8;
  ull acc[4][4];
  #pragma unroll
  for (int i=0;i<4;i++){ acc[i][0]=0; acc[i][1]=0; acc[i][2]=0; acc[i][3]=0; }

  for (int tile = blockIdx.x; tile < NNODE/32; tile += gridDim.x){
    int base = tile*32;
    __syncthreads();
    for (int i=t; i<32*HNUM/4; i+=256)
      ((float4*)sH)[i] = ((const float4*)g_allH)[(size_t)base*32 + i];
    for (int i=t; i<32*DLAT/4; i+=256)
      ((float4*)sC)[i] = ((const float4*)g_cur)[(size_t)base*16 + i];
    __syncthreads();
    #pragma unroll 4
    for (int r=0;r<32;r++){
      float4 a  = *(const float4*)&sH[r*HNUM + h0];
      float4 b0 = *(const float4*)&sC[r*DLAT + d0];
      float4 b1 = *(const float4*)&sC[r*DLAT + d0 + 4];
      ull bp0=pack2(b0.x,b0.y), bp1=pack2(b0.z,b0.w);
      ull bp2=pack2(b1.x,b1.y), bp3=pack2(b1.z,b1.w);
      #pragma unroll
      for (int hi=0;hi<4;hi++){
        float av = (hi==0)?a.x:(hi==1)?a.y:(hi==2)?a.z:a.w;
        ull ad = pack2(av,av);
        acc[hi][0]=ffma2(acc[hi][0],ad,bp0);
        acc[hi][1]=ffma2(acc[hi][1],ad,bp1);
        acc[hi][2]=ffma2(acc[hi][2],ad,bp2);
        acc[hi][3]=ffma2(acc[hi][3],ad,bp3);
      }
    }
  }
  #pragma unroll
  for (int hi=0;hi<4;hi++)
    #pragma unroll
    for (int p=0;p<4;p++){
      float2 v = unpack2(acc[hi][p]);
      atomicAdd(&g_lat[(h0+hi)*DLAT + d0 + 2*p    ], v.x);
      atomicAdd(&g_lat[(h0+hi)*DLAT + d0 + 2*p + 1], v.y);
    }
}

// ===========================================================================
// k_hl: hl = leaky( allH[N,128] @ leaky(lat)[128,64] )
//   out[1+L] = hl ; if L==0: cur = hl+tem, gx = cur*aij ; if L==1: out[0]=tem
// Block 128 thr, tile M=128 N=64, K chunked by 32. Thread 8x8, f32x2.
// ===========================================================================
__global__ void __launch_bounds__(128, 4) k_hl(float* __restrict__ out, int layer){
  __shared__ float sLat[HNUM*DLAT];   // 32KB [k][n]
  __shared__ float sAc[128*32];       // 16KB [m][kchunk] swizzled
  int t = threadIdx.x;
  int R = blockIdx.x*128;
  for (int i=t; i<HNUM*DLAT; i+=128) sLat[i] = lrelu(g_lat[i]);

  int tm = t>>3, tn = t&7;            // 16 m-groups x 8 n-groups
  int m0 = tm*8, n0 = tn*8;
  ull acc[8][4];
  #pragma unroll
  for (int j=0;j<8;j++){ acc[j][0]=0; acc[j][1]=0; acc[j][2]=0; acc[j][3]=0; }

  for (int ch=0; ch<4; ch++){
    __syncthreads();
    #pragma unroll
    for (int i=0;i<8;i++){
      int slot = i*128 + t;           // 1024 = 128 rows x 8 quads
      int m = slot>>3, kc = slot&7;
      int r = R + m;
      float4 v = make_float4(0.f,0.f,0.f,0.f);
      if (r < NNODE) v = *(const float4*)&g_allH[(size_t)r*HNUM + ch*32 + kc*4];
      *(float4*)&sAc[m*32 + ((kc ^ ((m>>3)&7))<<2)] = v;
    }
    __syncthreads();
    #pragma unroll
    for (int kq=0;kq<8;kq++){
      float4 aq[8];
      int sw = (kq ^ (tm&7)) << 2;
      #pragma unroll
      for (int j=0;j<8;j++) aq[j] = *(const float4*)&sAc[(m0+j)*32 + sw];
      #pragma unroll
      for (int c=0;c<4;c++){
        int k = ch*32 + kq*4 + c;
        float4 b0 = *(const float4*)&sLat[k*DLAT + n0];
        float4 b1 = *(const float4*)&sLat[k*DLAT + n0 + 4];
        ull bp0=pack2(b0.x,b0.y), bp1=pack2(b0.z,b0.w);
        ull bp2=pack2(b1.x,b1.y), bp3=pack2(b1.z,b1.w);
        #pragma unroll
        for (int j=0;j<8;j++){
          float av = (c==0)?aq[j].x:(c==1)?aq[j].y:(c==2)?aq[j].z:aq[j].w;
          ull ad = pack2(av,av);
          acc[j][0]=ffma2(acc[j][0],ad,bp0);
          acc[j][1]=ffma2(acc[j][1],ad,bp1);
          acc[j][2]=ffma2(acc[j][2],ad,bp2);
          acc[j][3]=ffma2(acc[j][3],ad,bp3);
        }
      }
    }
  }
  float* o1 = out + (size_t)(1+layer)*N64;
  #pragma unroll
  for (int j=0;j<8;j++){
    int r = R + m0 + j;
    if (r < NNODE){
      float2 v0=unpack2(acc[j][0]), v1=unpack2(acc[j][1]);
      float2 v2=unpack2(acc[j][2]), v3=unpack2(acc[j][3]);
      float4 h0 = make_float4(lrelu(v0.x),lrelu(v0.y),lrelu(v1.x),lrelu(v1.y));
      float4 h1 = make_float4(lrelu(v2.x),lrelu(v2.y),lrelu(v3.x),lrelu(v3.y));
      *(float4*)&o1[(size_t)r*DLAT + n0]     = h0;
      *(float4*)&o1[(size_t)r*DLAT + n0 + 4] = h1;
      float4 t0 = *(const float4*)&g_tem[(size_t)r*DLAT + n0];
      float4 t1 = *(const float4*)&g_tem[(size_t)r*DLAT + n0 + 4];
      if (layer == 0){
        float4 c0 = make_float4(h0.x+t0.x, h0.y+t0.y, h0.z+t0.z, h0.w+t0.w);
        float4 c1 = make_float4(h1.x+t1.x, h1.y+t1.y, h1.z+t1.z, h1.w+t1.w);
        *(float4*)&g_cur[(size_t)r*DLAT + n0]     = c0;
        *(float4*)&g_cur[(size_t)r*DLAT + n0 + 4] = c1;
        float4 a0 = *(const float4*)&g_aij[(size_t)r*DLAT + n0];
        float4 a1 = *(const float4*)&g_aij[(size_t)r*DLAT + n0 + 4];
        *(float4*)&g_gx[(size_t)r*DLAT + n0]     = make_float4(c0.x*a0.x,c0.y*a0.y,c0.z*a0.z,c0.w*a0.w);
        *(float4*)&g_gx[(size_t)r*DLAT + n0 + 4] = make_float4(c1.x*a1.x,c1.y*a1.y,c1.z*a1.z,c1.w*a1.w);
      } else {
        *(float4*)&out[(size_t)r*DLAT + n0]     = t0;
        *(float4*)&out[(size_t)r*DLAT + n0 + 4] = t1;
      }
    }
  }
}

extern "C" void kernel_launch(void* const* d_in, const int* in_sizes, int n_in,
                              void* d_out, int out_size){
  const int*   rows = (const int*)  d_in[0];
  const int*   cols = (const int*)  d_in[1];
  const float* vals = (const float*)d_in[2];
  const float* u    = (const float*)d_in[3];
  const float* it   = (const float*)d_in[4];
  const float* Hy   = (const float*)d_in[5];
  const float* z    = (const float*)d_in[6];
  // d_in[7] = keepRate == 1 (static: no dropout path)
  float* out = (float*)d_out;

  k_allH<<<1563,128>>>(u, it, z, Hy);   // fused prep + cnt zero + allH GEMM
  k_hist<<<6250,256>>>(rows);
  k_scanA<<<NBLK,256>>>();
  k_scanB<<<1,512>>>();
  k_scanC<<<NBLK,256>>>();
  k_scatter<<<6250,256>>>(rows, cols, vals);
  for (int L=0; L<2; L++){
    k_spmm<<<12500,256>>>();
    k_lat<<<296,256>>>();
    k_hl<<<782,128>>>(out, L);
  }
  (void)in_sizes; (void)n_in; (void)out_size;
}

// round 4
// speedup vs baseline: 1.6948x; 1.0381x over previous
#include <cuda_runtime.h>
#include <math.h>

#define USERN 50000
#define NNODE 100000
#define DLAT  64
#define HNUM  128
#define NE    1600000
#define N64   (NNODE*DLAT)
#define NBLK  391          // ceil(NNODE/256)

// scratch (static device globals: allocation-free per harness rules)
__device__ float g_cur[N64];
__device__ float g_aij[N64];
__device__ float g_gx[N64];
__device__ float g_tem[N64];
__device__ float g_allH[NNODE*HNUM];
__device__ float g_lat[HNUM*DLAT];
__device__ int   g_cnt[NNODE];
__device__ int   g_fill[NNODE];
__device__ int   g_rowptr[NNODE+1];
__device__ int   g_bsum[NBLK];
__device__ int   g_boff[NBLK];
__device__ unsigned long long g_epack[NE];

typedef unsigned long long ull;

__device__ __forceinline__ float lrelu(float x){ return x > 0.f ? x : 0.5f*x; }

// tanh(x/2) = 2*sigmoid(x)-1, via exp(-|x|)
__device__ __forceinline__ float tanh_half(float x){
  float t = __expf(-fabsf(x));
  float r = __fdividef(1.f - t, 1.f + t);
  return copysignf(r, x);
}

// ---- packed f32x2 FMA helpers (Blackwell) ----
__device__ __forceinline__ ull ffma2(ull d, ull a, ull b){
  asm("fma.rn.f32x2 %0, %1, %2, %0;" : "+l"(d) : "l"(a), "l"(b));
  return d;
}
__device__ __forceinline__ ull pack2(float x, float y){
  ull r; asm("mov.b64 %0, {%1, %2};" : "=l"(r) : "f"(x), "f"(y)); return r;
}
__device__ __forceinline__ float2 unpack2(ull v){
  float2 r; asm("mov.b64 {%0, %1}, %2;" : "=f"(r.x), "=f"(r.y) : "l"(v)); return r;
}

// zero CSR counters
__global__ void __launch_bounds__(1024) k_zero(){
  int i = blockIdx.x*1024 + threadIdx.x;
  if (i < NNODE) g_cnt[i] = 0;
}

// ===========================================================================
// k_allH: allH[N,128] = cur[N,64] @ Hyper[64,128], fused with prep:
//   cur = concat(u,i); aij = tanh(z/2); gx = cur*aij
// Block: 128 thr, tile M=64 N=128 K=64. Thread: 8x8. f32x2 FMA.
// sA [m][k] with XOR-swizzled k-quad: phys_kq = kq ^ (m>>3)  (conflict-free)
// ===========================================================================
__global__ void __launch_bounds__(128, 4) k_allH(const float* __restrict__ u,
                                                 const float* __restrict__ it,
                                                 const float* __restrict__ z,
                                                 const float* __restrict__ Hyp){
  __shared__ float sA[64*64];    // 16KB [m][k] swizzled
  __shared__ float sB[64*HNUM];  // 32KB [k][n]
  int t = threadIdx.x;
  int R = blockIdx.x*64;

  for (int i=t; i<64*HNUM/4; i+=128) ((float4*)sB)[i] = ((const float4*)Hyp)[i];

  #pragma unroll
  for (int i=0;i<8;i++){
    int slot = i*128 + t;              // 1024 slots = 64 rows x 16 quads
    int m = slot>>4, kc = slot&15;
    int r = R + m;
    float4 v = make_float4(0.f,0.f,0.f,0.f);
    if (r < NNODE){
      const float4* src = (r < USERN) ? ((const float4*)u) + (size_t)r*16
                                      : ((const float4*)it) + (size_t)(r-USERN)*16;
      v = src[kc];
    }
    *(float4*)&sA[m*64 + ((kc ^ (m>>3))<<2)] = v;
    if (r < NNODE){
      ((float4*)g_cur)[(size_t)r*16 + kc] = v;
      float4 zz = ((const float4*)z)[(size_t)r*16 + kc];
      float4 a4; a4.x=tanh_half(zz.x); a4.y=tanh_half(zz.y);
                 a4.z=tanh_half(zz.z); a4.w=tanh_half(zz.w);
      ((float4*)g_aij)[(size_t)r*16 + kc] = a4;
      float4 g; g.x=v.x*a4.x; g.y=v.y*a4.y; g.z=v.z*a4.z; g.w=v.w*a4.w;
      ((float4*)g_gx)[(size_t)r*16 + kc] = g;
    }
  }
  __syncthreads();

  int tm = t>>4, tn = t&15;            // 8 m-groups x 16 n-groups
  int m0 = tm*8, n0 = tn*8;
  ull acc[8][4];
  #pragma unroll
  for (int j=0;j<8;j++){ acc[j][0]=0; acc[j][1]=0; acc[j][2]=0; acc[j][3]=0; }

  #pragma unroll
  for (int kq=0;kq<16;kq++){
    float4 aq[8];
    int sw = (kq ^ tm) << 2;           // (m0+j)>>3 == tm for j<8
    #pragma unroll
    for (int j=0;j<8;j++) aq[j] = *(const float4*)&sA[(m0+j)*64 + sw];
    #pragma unroll
    for (int c=0;c<4;c++){
      int k = kq*4+c;
      float4 b0 = *(const float4*)&sB[k*HNUM + n0];
      float4 b1 = *(const float4*)&sB[k*HNUM + n0 + 4];
      ull bp0=pack2(b0.x,b0.y), bp1=pack2(b0.z,b0.w);
      ull bp2=pack2(b1.x,b1.y), bp3=pack2(b1.z,b1.w);
      #pragma unroll
      for (int j=0;j<8;j++){
        float av = (c==0)?aq[j].x:(c==1)?aq[j].y:(c==2)?aq[j].z:aq[j].w;
        ull ad = pack2(av,av);
        acc[j][0]=ffma2(acc[j][0],ad,bp0);
        acc[j][1]=ffma2(acc[j][1],ad,bp1);
        acc[j][2]=ffma2(acc[j][2],ad,bp2);
        acc[j][3]=ffma2(acc[j][3],ad,bp3);
      }
    }
  }
  #pragma unroll
  for (int j=0;j<8;j++){
    int r = R + m0 + j;
    if (r < NNODE){
      float2 v0=unpack2(acc[j][0]), v1=unpack2(acc[j][1]);
      float2 v2=unpack2(acc[j][2]), v3=unpack2(acc[j][3]);
      *(float4*)&g_allH[(size_t)r*HNUM + n0]     = make_float4(v0.x,v0.y,v1.x,v1.y);
      *(float4*)&g_allH[(size_t)r*HNUM + n0 + 4] = make_float4(v2.x,v2.y,v3.x,v3.y);
    }
  }
}

// ===========================================================================
// CSR build: hist -> 3-stage scan -> scatter (packed 8B edge records)
// ===========================================================================
__global__ void __launch_bounds__(256) k_hist(const int* __restrict__ rows){
  int e = blockIdx.x*256 + threadIdx.x;            // grid == NE exactly
  atomicAdd(&g_cnt[rows[e]], 1);
}

__global__ void __launch_bounds__(256) k_scanA(){
  int idx = blockIdx.x*256 + threadIdx.x;
  int c = (idx < NNODE) ? g_cnt[idx] : 0;
  int lane = threadIdx.x&31, wid = threadIdx.x>>5;
  #pragma unroll
  for (int off=16;off;off>>=1) c += __shfl_down_sync(0xffffffffu, c, off);
  __shared__ int ws[8];
  if (lane==0) ws[wid]=c;
  __syncthreads();
  if (threadIdx.x==0){ int s=0; for(int i=0;i<8;i++) s+=ws[i]; g_bsum[blockIdx.x]=s; }
}

__global__ void __launch_bounds__(512) k_scanB(){
  __shared__ int s[512];
  int t = threadIdx.x;
  int v0 = (t < NBLK) ? g_bsum[t] : 0;
  s[t] = v0; __syncthreads();
  for (int off=1;off<512;off<<=1){
    int v = (t>=off) ? s[t-off] : 0;
    __syncthreads(); s[t]+=v; __syncthreads();
  }
  if (t < NBLK) g_boff[t] = s[t] - v0;             // exclusive
  if (t==0) g_rowptr[NNODE] = NE;
}

__global__ void __launch_bounds__(256) k_scanC(){
  int b = blockIdx.x, t = threadIdx.x;
  int idx = b*256 + t;
  int c = (idx < NNODE) ? g_cnt[idx] : 0;
  int lane = t&31, wid = t>>5;
  int incl = c;
  #pragma unroll
  for (int off=1;off<32;off<<=1){
    int y = __shfl_up_sync(0xffffffffu, incl, off);
    if (lane>=off) incl += y;
  }
  __shared__ int ws[8];
  if (lane==31) ws[wid]=incl;
  __syncthreads();
  if (t < 8){
    int v = ws[t], s = v;
    #pragma unroll
    for (int off=1;off<8;off<<=1){
      int y = __shfl_up_sync(0xffu, s, off);
      if (t>=off) s += y;
    }
    ws[t] = s - v;
  }
  __syncthreads();
  int excl = incl - c + ws[wid] + g_boff[b];
  if (idx < NNODE){ g_rowptr[idx] = excl; g_fill[idx] = excl; }
}

__global__ void __launch_bounds__(256) k_scatter(const int* __restrict__ rows,
                                                 const int* __restrict__ cols,
                                                 const float* __restrict__ vals){
  int e = blockIdx.x*256 + threadIdx.x;            // grid == NE exactly
  int r = rows[e];
  int p = atomicAdd(&g_fill[r], 1);
  g_epack[p] = ((ull)__float_as_uint(vals[e])<<32) | (unsigned)cols[e];
}

// ===========================================================================
// k_spmm: tem[r,:] = leaky( sum_e val*gx[col,:] ), HALF-WARP (16 lanes) per row.
// Lane holds float4 (16B) -> 1 LDG.128 per edge per lane; manual 4x unroll
// batches 4 edge-record loads then 4 independent gathers (MLP>=4).
// block 0 also zeroes g_lat for the upcoming k_lat.
// ===========================================================================
__global__ void __launch_bounds__(256) k_spmm(){
  if (blockIdx.x == 0){
    for (int i=threadIdx.x; i<HNUM*DLAT; i+=256) g_lat[i] = 0.f;
  }
  int r    = (blockIdx.x*256 + threadIdx.x) >> 4;  // 6250 blocks * 16 rows == NNODE
  int lane = threadIdx.x & 15;
  int beg = g_rowptr[r], end = g_rowptr[r+1];
  float4 acc = make_float4(0.f,0.f,0.f,0.f);
  int j = beg;
  for (; j+4 <= end; j+=4){
    ull p0 = g_epack[j  ];
    ull p1 = g_epack[j+1];
    ull p2 = g_epack[j+2];
    ull p3 = g_epack[j+3];
    int c0 = (int)(unsigned)p0; float v0 = __uint_as_float((unsigned)(p0>>32));
    int c1 = (int)(unsigned)p1; float v1 = __uint_as_float((unsigned)(p1>>32));
    int c2 = (int)(unsigned)p2; float v2 = __uint_as_float((unsigned)(p2>>32));
    int c3 = (int)(unsigned)p3; float v3 = __uint_as_float((unsigned)(p3>>32));
    float4 x0 = *(const float4*)&g_gx[(size_t)c0*DLAT + lane*4];
    float4 x1 = *(const float4*)&g_gx[(size_t)c1*DLAT + lane*4];
    float4 x2 = *(const float4*)&g_gx[(size_t)c2*DLAT + lane*4];
    float4 x3 = *(const float4*)&g_gx[(size_t)c3*DLAT + lane*4];
    acc.x = fmaf(v0,x0.x,acc.x); acc.y = fmaf(v0,x0.y,acc.y);
    acc.z = fmaf(v0,x0.z,acc.z); acc.w = fmaf(v0,x0.w,acc.w);
    acc.x = fmaf(v1,x1.x,acc.x); acc.y = fmaf(v1,x1.y,acc.y);
    acc.z = fmaf(v1,x1.z,acc.z); acc.w = fmaf(v1,x1.w,acc.w);
    acc.x = fmaf(v2,x2.x,acc.x); acc.y = fmaf(v2,x2.y,acc.y);
    acc.z = fmaf(v2,x2.z,acc.z); acc.w = fmaf(v2,x2.w,acc.w);
    acc.x = fmaf(v3,x3.x,acc.x); acc.y = fmaf(v3,x3.y,acc.y);
    acc.z = fmaf(v3,x3.z,acc.z); acc.w = fmaf(v3,x3.w,acc.w);
  }
  for (; j < end; j++){
    ull p = g_epack[j];
    int   c = (int)(unsigned)p;
    float v = __uint_as_float((unsigned)(p>>32));
    float4 x = *(const float4*)&g_gx[(size_t)c*DLAT + lane*4];
    acc.x = fmaf(v,x.x,acc.x); acc.y = fmaf(v,x.y,acc.y);
    acc.z = fmaf(v,x.z,acc.z); acc.w = fmaf(v,x.w,acc.w);
  }
  float4 o; o.x=lrelu(acc.x); o.y=lrelu(acc.y); o.z=lrelu(acc.z); o.w=lrelu(acc.w);
  *(float4*)&g_tem[(size_t)r*DLAT + lane*4] = o;
}

// ===========================================================================
// k_lat: lat[128,64] += allH^T @ cur  (reduce over N rows; atomics at end)
// 256 thr, thread = 4H x 8D; 32-row smem tiles; f32x2 FMA.
// ===========================================================================
__global__ void __launch_bounds__(256) k_lat(){
  __shared__ float sH[32*HNUM];   // 16KB
  __shared__ float sC[32*DLAT];   // 8KB
  int t = threadIdx.x;
  int th = t>>3, td = t&7;        // 32 h-groups x 8 d-groups
  int h0 = th*4, d0 = td*8;
  ull acc[4][4];
  #pragma unroll
  for (int i=0;i<4;i++){ acc[i][0]=0; acc[i][1]=0; acc[i][2]=0; acc[i][3]=0; }

  for (int tile = blockIdx.x; tile < NNODE/32; tile += gridDim.x){
    int base = tile*32;
    __syncthreads();
    for (int i=t; i<32*HNUM/4; i+=256)
      ((float4*)sH)[i] = ((const float4*)g_allH)[(size_t)base*32 + i];
    for (int i=t; i<32*DLAT/4; i+=256)
      ((float4*)sC)[i] = ((const float4*)g_cur)[(size_t)base*16 + i];
    __syncthreads();
    #pragma unroll 4
    for (int r=0;r<32;r++){
      float4 a  = *(const float4*)&sH[r*HNUM + h0];
      float4 b0 = *(const float4*)&sC[r*DLAT + d0];
      float4 b1 = *(const float4*)&sC[r*DLAT + d0 + 4];
      ull bp0=pack2(b0.x,b0.y), bp1=pack2(b0.z,b0.w);
      ull bp2=pack2(b1.x,b1.y), bp3=pack2(b1.z,b1.w);
      #pragma unroll
      for (int hi=0;hi<4;hi++){
        float av = (hi==0)?a.x:(hi==1)?a.y:(hi==2)?a.z:a.w;
        ull ad = pack2(av,av);
        acc[hi][0]=ffma2(acc[hi][0],ad,bp0);
        acc[hi][1]=ffma2(acc[hi][1],ad,bp1);
        acc[hi][2]=ffma2(acc[hi][2],ad,bp2);
        acc[hi][3]=ffma2(acc[hi][3],ad,bp3);
      }
    }
  }
  #pragma unroll
  for (int hi=0;hi<4;hi++)
    #pragma unroll
    for (int p=0;p<4;p++){
      float2 v = unpack2(acc[hi][p]);
      atomicAdd(&g_lat[(h0+hi)*DLAT + d0 + 2*p    ], v.x);
      atomicAdd(&g_lat[(h0+hi)*DLAT + d0 + 2*p + 1], v.y);
    }
}

// ===========================================================================
// k_hl: hl = leaky( allH[N,128] @ leaky(lat)[128,64] )
//   out[1+L] = hl ; if L==0: cur = hl+tem, gx = cur*aij ; if L==1: out[0]=tem
// Block 128 thr, tile M=128 N=64, K chunked by 32. Thread 8x8, f32x2.
// ===========================================================================
__global__ void __launch_bounds__(128, 4) k_hl(float* __restrict__ out, int layer){
  __shared__ float sLat[HNUM*DLAT];   // 32KB [k][n]
  __shared__ float sAc[128*32];       // 16KB [m][kchunk] swizzled
  int t = threadIdx.x;
  int R = blockIdx.x*128;
  for (int i=t; i<HNUM*DLAT; i+=128) sLat[i] = lrelu(g_lat[i]);

  int tm = t>>3, tn = t&7;            // 16 m-groups x 8 n-groups
  int m0 = tm*8, n0 = tn*8;
  ull acc[8][4];
  #pragma unroll
  for (int j=0;j<8;j++){ acc[j][0]=0; acc[j][1]=0; acc[j][2]=0; acc[j][3]=0; }

  for (int ch=0; ch<4; ch++){
    __syncthreads();
    #pragma unroll
    for (int i=0;i<8;i++){
      int slot = i*128 + t;           // 1024 = 128 rows x 8 quads
      int m = slot>>3, kc = slot&7;
      int r = R + m;
      float4 v = make_float4(0.f,0.f,0.f,0.f);
      if (r < NNODE) v = *(const float4*)&g_allH[(size_t)r*HNUM + ch*32 + kc*4];
      *(float4*)&sAc[m*32 + ((kc ^ ((m>>3)&7))<<2)] = v;
    }
    __syncthreads();
    #pragma unroll
    for (int kq=0;kq<8;kq++){
      float4 aq[8];
      int sw = (kq ^ (tm&7)) << 2;
      #pragma unroll
      for (int j=0;j<8;j++) aq[j] = *(const float4*)&sAc[(m0+j)*32 + sw];
      #pragma unroll
      for (int c=0;c<4;c++){
        int k = ch*32 + kq*4 + c;
        float4 b0 = *(const float4*)&sLat[k*DLAT + n0];
        float4 b1 = *(const float4*)&sLat[k*DLAT + n0 + 4];
        ull bp0=pack2(b0.x,b0.y), bp1=pack2(b0.z,b0.w);
        ull bp2=pack2(b1.x,b1.y), bp3=pack2(b1.z,b1.w);
        #pragma unroll
        for (int j=0;j<8;j++){
          float av = (c==0)?aq[j].x:(c==1)?aq[j].y:(c==2)?aq[j].z:aq[j].w;
          ull ad = pack2(av,av);
          acc[j][0]=ffma2(acc[j][0],ad,bp0);
          acc[j][1]=ffma2(acc[j][1],ad,bp1);
          acc[j][2]=ffma2(acc[j][2],ad,bp2);
          acc[j][3]=ffma2(acc[j][3],ad,bp3);
        }
      }
    }
  }
  float* o1 = out + (size_t)(1+layer)*N64;
  #pragma unroll
  for (int j=0;j<8;j++){
    int r = R + m0 + j;
    if (r < NNODE){
      float2 v0=unpack2(acc[j][0]), v1=unpack2(acc[j][1]);
      float2 v2=unpack2(acc[j][2]), v3=unpack2(acc[j][3]);
      float4 h0 = make_float4(lrelu(v0.x),lrelu(v0.y),lrelu(v1.x),lrelu(v1.y));
      float4 h1 = make_float4(lrelu(v2.x),lrelu(v2.y),lrelu(v3.x),lrelu(v3.y));
      *(float4*)&o1[(size_t)r*DLAT + n0]     = h0;
      *(float4*)&o1[(size_t)r*DLAT + n0 + 4] = h1;
      float4 t0 = *(const float4*)&g_tem[(size_t)r*DLAT + n0];
      float4 t1 = *(const float4*)&g_tem[(size_t)r*DLAT + n0 + 4];
      if (layer == 0){
        float4 c0 = make_float4(h0.x+t0.x, h0.y+t0.y, h0.z+t0.z, h0.w+t0.w);
        float4 c1 = make_float4(h1.x+t1.x, h1.y+t1.y, h1.z+t1.z, h1.w+t1.w);
        *(float4*)&g_cur[(size_t)r*DLAT + n0]     = c0;
        *(float4*)&g_cur[(size_t)r*DLAT + n0 + 4] = c1;
        float4 a0 = *(const float4*)&g_aij[(size_t)r*DLAT + n0];
        float4 a1 = *(const float4*)&g_aij[(size_t)r*DLAT + n0 + 4];
        *(float4*)&g_gx[(size_t)r*DLAT + n0]     = make_float4(c0.x*a0.x,c0.y*a0.y,c0.z*a0.z,c0.w*a0.w);
        *(float4*)&g_gx[(size_t)r*DLAT + n0 + 4] = make_float4(c1.x*a1.x,c1.y*a1.y,c1.z*a1.z,c1.w*a1.w);
      } else {
        *(float4*)&out[(size_t)r*DLAT + n0]     = t0;
        *(float4*)&out[(size_t)r*DLAT + n0 + 4] = t1;
      }
    }
  }
}

extern "C" void kernel_launch(void* const* d_in, const int* in_sizes, int n_in,
                              void* d_out, int out_size){
  const int*   rows = (const int*)  d_in[0];
  const int*   cols = (const int*)  d_in[1];
  const float* vals = (const float*)d_in[2];
  const float* u    = (const float*)d_in[3];
  const float* it   = (const float*)d_in[4];
  const float* Hy   = (const float*)d_in[5];
  const float* z    = (const float*)d_in[6];
  // d_in[7] = keepRate == 1 (static: no dropout path)
  float* out = (float*)d_out;

  k_zero<<<98,1024>>>();                 // idx 0
  k_hist<<<6250,256>>>(rows);            // idx 1
  k_scanA<<<NBLK,256>>>();               // idx 2
  k_allH<<<1563,128>>>(u, it, z, Hy);    // idx 3  <- profiled slot
  k_scanB<<<1,512>>>();                  // idx 4
  k_scanC<<<NBLK,256>>>();               // idx 5
  k_scatter<<<6250,256>>>(rows, cols, vals);
  for (int L=0; L<2; L++){
    k_spmm<<<6250,256>>>();
    k_lat<<<296,256>>>();
    k_hl<<<782,128>>>(out, L);
  }
  (void)in_sizes; (void)n_in; (void)out_size;
}